// round 17
// baseline (speedup 1.0000x reference)
#include <cuda_runtime.h>
#include <math.h>
#include <stdint.h>

#define DIM 256
#define NROWS 4096
#define QSCALE  25.0f
#define INV_S2  (1.0f / (QSCALE * QSCALE))
#define PAIR_BLOCKS 512

// ---- static device scratch (no allocations allowed) ----
__device__ int8_t       g_Xq[NROWS * DIM];            // 1 MB int8 table
__device__ float        g_norm[NROWS];                // raw Sum(q^2) as float
__device__ float        g_G[(size_t)NROWS * NROWS];   // raw int Gram as float (lower-tri valid)
__device__ float2       g_part[PAIR_BLOCKS];          // per-block (pos, neg) partials

// ============================================================================
// Prep: fp32 -> int8 quantize (scale 25, clamp ±127), integer row norms.
// One warp per row.
// ============================================================================
__device__ __forceinline__ int q8(float x) {
    return __float2int_rn(fminf(fmaxf(x * QSCALE, -127.0f), 127.0f));
}

__global__ void __launch_bounds__(256)
prep_kernel(const float* __restrict__ X)
{
    const int warp = threadIdx.x >> 5;
    const int lane = threadIdx.x & 31;
    const int row  = blockIdx.x * 8 + warp;

    const float4* src = (const float4*)(X + (size_t)row * DIM);
    float4 v0 = src[lane * 2];
    float4 v1 = src[lane * 2 + 1];

    int q0 = q8(v0.x), q1 = q8(v0.y), q2 = q8(v0.z), q3 = q8(v0.w);
    int q4 = q8(v1.x), q5 = q8(v1.y), q6 = q8(v1.z), q7 = q8(v1.w);

    unsigned lo = (q0 & 0xFF) | ((q1 & 0xFF) << 8) | ((q2 & 0xFF) << 16) | ((q3 & 0xFF) << 24);
    unsigned hi = (q4 & 0xFF) | ((q5 & 0xFF) << 8) | ((q6 & 0xFF) << 16) | ((q7 & 0xFF) << 24);
    *(uint2*)(g_Xq + (size_t)row * DIM + lane * 8) = make_uint2(lo, hi);

    int s = q0 * q0 + q1 * q1 + q2 * q2 + q3 * q3
          + q4 * q4 + q5 * q5 + q6 * q6 + q7 * q7;
    #pragma unroll
    for (int off = 16; off > 0; off >>= 1)
        s += __shfl_xor_sync(0xFFFFFFFFu, s, off);
    if (lane == 0) g_norm[row] = (float)s;
}

// ============================================================================
// Gram GEMM: G = Xq * Xq^T (s8 in, s32 acc) via mma.sync.m16n8k32 + ldmatrix.
// 528 lower-triangle 128x128 tiles; 8 warps of 64x32; K staged 128B x 2.
// SMEM rows padded to 144 B (16 B shift per row -> conflict-free LDSM).
// ============================================================================
#define KCHUNK  128
#define SSTRIDE 144

__device__ __forceinline__ void imma16832(int c[4], const unsigned a[4],
                                          const unsigned b0, const unsigned b1)
{
    asm volatile(
        "mma.sync.aligned.m16n8k32.row.col.s32.s8.s8.s32 "
        "{%0,%1,%2,%3}, {%4,%5,%6,%7}, {%8,%9}, {%0,%1,%2,%3};\n"
        : "+r"(c[0]), "+r"(c[1]), "+r"(c[2]), "+r"(c[3])
        : "r"(a[0]), "r"(a[1]), "r"(a[2]), "r"(a[3]),
          "r"(b0), "r"(b1));
}

__device__ __forceinline__ void ldsm_x4(unsigned r[4], const void* p) {
    unsigned addr = (unsigned)__cvta_generic_to_shared(p);
    asm volatile("ldmatrix.sync.aligned.m8n8.x4.shared.b16 {%0,%1,%2,%3}, [%4];"
                 : "=r"(r[0]), "=r"(r[1]), "=r"(r[2]), "=r"(r[3]) : "r"(addr));
}

__global__ void __launch_bounds__(256, 2)
gram_i8_kernel()
{
    // linear bid -> lower-triangle (bm, bn), bm >= bn
    const int bid = blockIdx.x;
    int bm = (int)((sqrtf(8.0f * (float)bid + 1.0f) - 1.0f) * 0.5f);
    while ((bm + 1) * (bm + 2) / 2 <= bid) ++bm;
    while (bm * (bm + 1) / 2 > bid)        --bm;
    const int bn = bid - bm * (bm + 1) / 2;

    __shared__ char As[128 * SSTRIDE];   // 18 KB
    __shared__ char Bs[128 * SSTRIDE];   // 18 KB

    const int tid  = threadIdx.x;
    const int warp = tid >> 5;
    const int lane = tid & 31;
    const int wm   = warp >> 2;      // 0..1  (64-row slabs)
    const int wn   = warp & 3;       // 0..3  (32-col slabs)
    const int tg   = lane >> 2;      // 0..7
    const int tq   = lane & 3;       // 0..3

    int acc[4][4][4];
    #pragma unroll
    for (int mi = 0; mi < 4; ++mi)
        #pragma unroll
        for (int ni = 0; ni < 4; ++ni)
            #pragma unroll
            for (int k = 0; k < 4; ++k) acc[mi][ni][k] = 0;

    const int rowA = bm * 128;
    const int rowB = bn * 128;

    const int l_row = lane & 15;
    const int l_col = (lane >> 4) << 4;

    for (int kc = 0; kc < 2; ++kc) {
        const int kbase = kc * KCHUNK;
        // stage 128 rows x 128 B per matrix = 1024 uint4 each: 256 thr x 4 it
        #pragma unroll
        for (int it = 0; it < 4; ++it) {
            const int t = tid + it * 256;        // 0..1023
            const int r = t >> 3;                // 8 x 16B per 128-B row -> rows 0..127
            const int c = (t & 7) << 4;
            *(uint4*)(As + r * SSTRIDE + c) =
                *(const uint4*)(g_Xq + (size_t)(rowA + r) * DIM + kbase + c);
            *(uint4*)(Bs + r * SSTRIDE + c) =
                *(const uint4*)(g_Xq + (size_t)(rowB + r) * DIM + kbase + c);
        }
        __syncthreads();

        #pragma unroll
        for (int ks = 0; ks < 4; ++ks) {         // 4 x K32 steps per chunk
            const int kk = ks * 32;
            unsigned a[4][4], b[2][4];
            #pragma unroll
            for (int mi = 0; mi < 4; ++mi)
                ldsm_x4(a[mi], As + (wm * 64 + mi * 16 + l_row) * SSTRIDE + kk + l_col);
            #pragma unroll
            for (int g2 = 0; g2 < 2; ++g2)
                ldsm_x4(b[g2], Bs + (wn * 32 + g2 * 16 + l_row) * SSTRIDE + kk + l_col);

            #pragma unroll
            for (int mi = 0; mi < 4; ++mi)
                #pragma unroll
                for (int ni = 0; ni < 4; ++ni) {
                    const int g2 = ni >> 1, h = ni & 1;
                    imma16832(acc[mi][ni], a[mi], b[g2][h], b[g2][2 + h]);
                }
        }
        __syncthreads();
    }

    // epilogue: raw int Gram -> float
    #pragma unroll
    for (int mi = 0; mi < 4; ++mi) {
        const int r0 = bm * 128 + wm * 64 + mi * 16 + tg;
        #pragma unroll
        for (int ni = 0; ni < 4; ++ni) {
            const int c0 = bn * 128 + wn * 32 + ni * 8 + tq * 2;
            *(float2*)(&g_G[(size_t)r0 * NROWS + c0]) =
                make_float2((float)acc[mi][ni][0], (float)acc[mi][ni][1]);
            *(float2*)(&g_G[(size_t)(r0 + 8) * NROWS + c0]) =
                make_float2((float)acc[mi][ni][2], (float)acc[mi][ni][3]);
        }
    }
}

// ============================================================================
// Pair phase: d^2 = (n[r] + n[c] - 2*G[r][c]) / S^2.
// Per-block partials -> g_part[bid] via PLAIN stores (no atomics, no tickets).
// ============================================================================
__device__ __forceinline__ float softplus_fast(float z) {
    return fmaxf(z, 0.0f) + __logf(1.0f + __expf(-fabsf(z)));
}

__global__ void __launch_bounds__(256)
pair_kernel(const float* __restrict__ bias,
            const int*   __restrict__ pos_idx,
            const int*   __restrict__ neg_idx,
            int P)
{
    const int tid    = blockIdx.x * blockDim.x + threadIdx.x;
    const int stride = gridDim.x * blockDim.x;
    const float b    = bias[0];
    const int total  = 2 * P;

    float ap = 0.0f, an = 0.0f;
    for (int t = tid; t < total; t += stride) {
        const bool isp = (t < P);
        const int  p   = isp ? t : (t - P);
        const int2 ij  = ((const int2*)(isp ? pos_idx : neg_idx))[p];
        const int  r   = max(ij.x, ij.y);
        const int  c   = min(ij.x, ij.y);
        const float g  = __ldg(&g_G[(size_t)r * NROWS + c]);
        const float d  = (g_norm[r] + g_norm[c] - 2.0f * g) * INV_S2;
        const float z  = isp ? (d - b) : (b - d);
        const float sp = softplus_fast(z);
        if (isp) ap += sp; else an += sp;
    }

    #pragma unroll
    for (int off = 16; off > 0; off >>= 1) {
        ap += __shfl_xor_sync(0xFFFFFFFFu, ap, off);
        an += __shfl_xor_sync(0xFFFFFFFFu, an, off);
    }

    __shared__ float s_p[8], s_n[8];
    const int warp = threadIdx.x >> 5;
    const int lane = threadIdx.x & 31;
    if (lane == 0) { s_p[warp] = ap; s_n[warp] = an; }
    __syncthreads();

    if (threadIdx.x == 0) {
        float tp = 0.0f, tn = 0.0f;
        #pragma unroll
        for (int w = 0; w < 8; ++w) { tp += s_p[w]; tn += s_n[w]; }
        g_part[blockIdx.x] = make_float2(tp, tn);   // unique slot, plain store
    }
}

// ============================================================================
// Finalize: one warp sums all partials in a FIXED order -> bit-deterministic.
// ============================================================================
__global__ void finalize_kernel(float* __restrict__ out, float invP)
{
    const int lane = threadIdx.x;
    float p = 0.0f, n = 0.0f;
    #pragma unroll
    for (int i = 0; i < PAIR_BLOCKS / 32; ++i) {
        float2 v = g_part[lane + i * 32];
        p += v.x;
        n += v.y;
    }
    #pragma unroll
    for (int off = 16; off > 0; off >>= 1) {
        p += __shfl_xor_sync(0xFFFFFFFFu, p, off);
        n += __shfl_xor_sync(0xFFFFFFFFu, n, off);
    }
    if (lane == 0) {
        out[0] = p * invP;
        out[1] = n * invP;
    }
}

// ============================================================================
extern "C" void kernel_launch(void* const* d_in, const int* in_sizes, int n_in,
                              void* d_out, int out_size)
{
    const float* X       = (const float*)d_in[0];   // [4096, 256] fp32
    const float* bias    = (const float*)d_in[1];   // [1]
    const int*   pos_idx = (const int*)d_in[2];     // [P, 2]
    const int*   neg_idx = (const int*)d_in[3];     // [P, 2]
    float*       out     = (float*)d_out;           // [2]

    const int P = in_sizes[2] / 2;

    prep_kernel<<<NROWS / 8, 256>>>(X);

    const int nblk = 32 * 33 / 2;                   // 528 lower-tri tiles
    gram_i8_kernel<<<nblk, 256>>>();

    pair_kernel<<<PAIR_BLOCKS, 256>>>(bias, pos_idx, neg_idx, P);

    finalize_kernel<<<1, 32>>>(out, 1.0f / (float)P);
}